// round 9
// baseline (speedup 1.0000x reference)
#include <cuda_runtime.h>
#include <cuda_fp16.h>
#include <cstdint>

#define V_N 20000
#define V_PAD 20032      // 313 * 64
#define E_N 40000
#define E_PAD 40064      // 313 * 128
#define NT 313           // 128-row M tiles in ew gemm
#define NIN 74
#define EIN 12
#define D 64
#define EH 128
#define DD 4096
#define STEPS 6

// ---------------- scratch (static device globals; zero-initialized) ---------
__device__ float  d_h[V_PAD * D];
__device__ float  d_neigh[V_PAD * D];
__device__ __half d_z[E_PAD * EH];
__device__ __half d_ew[(size_t)E_PAD * DD];
__device__ __half d_Wg[256 * EH];              // packed GRU weights (fp16)

// ---------------- asm helpers -------------------------------------------------
__device__ __forceinline__ uint32_t smem_u32(const void* p) {
    uint32_t a;
    asm("{ .reg .u64 t; cvta.to.shared.u64 t, %1; cvt.u32.u64 %0, t; }" : "=r"(a) : "l"(p));
    return a;
}
__device__ __forceinline__ void cp16(uint32_t s, const void* g) {
    asm volatile("cp.async.cg.shared.global [%0], [%1], 16;" :: "r"(s), "l"(g));
}
#define CP_COMMIT() asm volatile("cp.async.commit_group;" ::: "memory")
#define CP_WAIT0()  asm volatile("cp.async.wait_group 0;" ::: "memory")

__device__ __forceinline__ void ldsm_x4(uint32_t addr, uint32_t& r0, uint32_t& r1,
                                        uint32_t& r2, uint32_t& r3) {
    asm volatile("ldmatrix.sync.aligned.m8n8.x4.shared.b16 {%0,%1,%2,%3}, [%4];"
                 : "=r"(r0), "=r"(r1), "=r"(r2), "=r"(r3) : "r"(addr));
}
__device__ __forceinline__ void ldsm_x2(uint32_t addr, uint32_t& r0, uint32_t& r1) {
    asm volatile("ldmatrix.sync.aligned.m8n8.x2.shared.b16 {%0,%1}, [%2];"
                 : "=r"(r0), "=r"(r1) : "r"(addr));
}
__device__ __forceinline__ void mma16816(float* c, const uint32_t* a, const uint32_t* b) {
    asm volatile("mma.sync.aligned.m16n8k16.row.col.f32.f16.f16.f32 "
                 "{%0,%1,%2,%3}, {%4,%5,%6,%7}, {%8,%9}, {%0,%1,%2,%3};"
                 : "+f"(c[0]), "+f"(c[1]), "+f"(c[2]), "+f"(c[3])
                 : "r"(a[0]), "r"(a[1]), "r"(a[2]), "r"(a[3]), "r"(b[0]), "r"(b[1]));
}

// ---------------- prep / small kernels ---------------------------------------
__global__ void prep_wg(const float* __restrict__ Wih, const float* __restrict__ Whh) {
    int idx = blockIdx.x * blockDim.x + threadIdx.x;
    if (idx >= 256 * EH) return;
    int r = idx >> 7, k = idx & 127;
    float v = 0.f;
    if (r < 128) {
        v = (k < 64) ? Wih[r * D + k] : Whh[r * D + (k - 64)];
    } else if (r < 192) {                // i_n: Wih rows 128..191
        if (k < 64) v = Wih[r * D + k];
    } else {                             // h_n: Whh rows 128..191
        if (k >= 64) v = Whh[(r - 64) * D + (k - 64)];
    }
    d_Wg[idx] = __float2half(v);
}

// h = relu(nf @ W^T + b); also zeroes d_neigh for these nodes (padded rows
// are never written by anyone, so they stay zero from static init).
__global__ void proj_kernel(const float* __restrict__ nf,
                            const float* __restrict__ W,
                            const float* __restrict__ b) {
    __shared__ float Ws[NIN][D];
    __shared__ float nfs[16][NIN + 2];
    __shared__ float bs[D];
    const int tid = threadIdx.x;
    const int v0 = blockIdx.x * 16;
    for (int idx = tid; idx < D * NIN; idx += 256) {
        int o = idx / NIN, i = idx % NIN;
        Ws[i][o] = W[idx];
    }
    for (int idx = tid; idx < 16 * NIN; idx += 256) {
        int n = idx / NIN, i = idx % NIN;
        nfs[n][i] = nf[(size_t)(v0 + n) * NIN + i];
    }
    if (tid < D) bs[tid] = b[tid];
    __syncthreads();
    const int o = tid & 63, g = tid >> 6;
    #pragma unroll
    for (int nn = 0; nn < 4; nn++) {
        int n = g * 4 + nn;
        float acc = bs[o];
        #pragma unroll
        for (int i = 0; i < NIN; i++) acc = fmaf(Ws[i][o], nfs[n][i], acc);
        d_h[(size_t)(v0 + n) * D + o] = fmaxf(acc, 0.f);
        d_neigh[(size_t)(v0 + n) * D + o] = 0.f;
    }
}

__global__ void zhid_kernel(const float* __restrict__ ef,
                            const float* __restrict__ W1,
                            const float* __restrict__ b1) {
    __shared__ float W1s[EIN][EH];
    __shared__ float b1s[EH];
    __shared__ float efs[16][EIN];
    const int tid = threadIdx.x;
    const int e0 = blockIdx.x * 16;
    for (int idx = tid; idx < EH * EIN; idx += 256) {
        int k = idx / EIN, i = idx % EIN;
        W1s[i][k] = W1[idx];
    }
    for (int idx = tid; idx < 16 * EIN; idx += 256) {
        int e = idx / EIN, i = idx % EIN;
        efs[e][i] = ef[(size_t)(e0 + e) * EIN + i];
    }
    if (tid < EH) b1s[tid] = b1[tid];
    __syncthreads();
    const int k = tid & 127, g = tid >> 7;
    #pragma unroll
    for (int ee = 0; ee < 8; ee++) {
        int e = g * 8 + ee;
        float acc = b1s[k];
        #pragma unroll
        for (int i = 0; i < EIN; i++) acc = fmaf(W1s[i][k], efs[e][i], acc);
        d_z[(size_t)(e0 + e) * EH + k] = __float2half(fmaxf(acc, 0.f));
    }
}

// ---------------- ew GEMM (PTX mma, B in registers) ---------------------------
// C[E_PAD,4096] = [z|1] @ [W2|b2]^T. Tile M=128 x N=128, K=144 (9 k16 chunks,
// chunk 8 = bias fold). Warp tile 32(M) x 64(N). B fragments loaded to regs
// ONCE per block (kills 147KB/tile duplicated B smem reads). fp16 smem-staged
// epilogue (Cs16 overlays Bs) -> int4 coalesced stores.
#define ASTR 152
#define BSTR 152
#define CSTR16 136
#define A_OFF   38912                          // Bs/Cs16 region = [0, 38912)
#define EW_SMEM (A_OFF + 128 * ASTR * 2)       // 77824
#define NSLABS 32
#define MGROUPS 4

__global__ __launch_bounds__(256, 1) void ew_gemm(const float* __restrict__ W2,
                                                  const float* __restrict__ b2) {
    extern __shared__ char smem[];
    __half* Bs   = (__half*)smem;
    __half* Cs16 = (__half*)smem;              // overlays Bs after B->regs
    __half* As   = (__half*)(smem + A_OFF);
    const uint32_t sbase = smem_u32(smem);
    const int tid  = threadIdx.x;
    const int lane = tid & 31;
    const int w    = tid >> 5;
    const int wm   = w & 3;        // 4 M groups of 32 rows
    const int wn   = w >> 2;       // 2 N groups of 64 cols
    const int n0   = blockIdx.x * 128;
    const int by   = blockIdx.y;

    // A constant tail: col 128 = 1, 129..143 = 0 (cp.async writes only cols<128)
    for (int q = tid; q < 2048; q += 256) {
        int r = q >> 4, k = 128 + (q & 15);
        As[r * ASTR + k] = (k == 128) ? __float2half(1.f) : __half(0);
    }
    // prefetch first A tile
    for (int q = tid; q < 2048; q += 256) {
        int r = q >> 4, c = (q & 15) * 8;
        cp16(sbase + A_OFF + (uint32_t)(r * ASTR + c) * 2,
             &d_z[(size_t)(by * 128 + r) * EH + c]);
    }
    CP_COMMIT();

    // stage B slab: 128 N-rows x 128 K (f32->f16) + bias col 128, zeros 129..143
    for (int q = tid; q < 4096; q += 256) {
        int n = q >> 5, k4 = (q & 31) * 4;
        float4 v = *(const float4*)&W2[(size_t)(n0 + n) * EH + k4];
        __half t4[4] = { __float2half(v.x), __float2half(v.y),
                         __float2half(v.z), __float2half(v.w) };
        *(uint2*)&Bs[n * BSTR + k4] = *(uint2*)t4;
    }
    for (int q = tid; q < 2048; q += 256) {
        int n = q >> 4, k = 128 + (q & 15);
        Bs[n * BSTR + k] = (k == 128) ? __float2half(b2[n0 + n]) : __half(0);
    }
    __syncthreads();

    // B -> registers: 9 kc x 8 n8-tiles x 2 regs = 144 regs per thread
    uint32_t b[9][8][2];
    {
        const int b_r = lane & 7, b_c = ((lane >> 3) & 1) * 8;
        #pragma unroll
        for (int kc = 0; kc < 9; kc++)
            #pragma unroll
            for (int j = 0; j < 8; j++)
                ldsm_x2(sbase + (uint32_t)((wn * 64 + j * 8 + b_r) * BSTR
                                           + kc * 16 + b_c) * 2,
                        b[kc][j][0], b[kc][j][1]);
    }
    __syncthreads();                          // Bs region now free (-> Cs16)

    const int a_r = lane & 15, a_c = (lane >> 4) * 8;
    const uint32_t aAddr0 = sbase + A_OFF + (uint32_t)((wm * 32 + a_r) * ASTR + a_c) * 2;

    const int TPT = (NT + MGROUPS - 1) / MGROUPS;
    for (int mt = 0; mt < TPT; mt++) {
        int t = by + MGROUPS * mt;
        if (t >= NT) break;
        CP_WAIT0();
        __syncthreads();                      // A ready

        float c[2][8][4];
        #pragma unroll
        for (int i = 0; i < 2; i++)
            #pragma unroll
            for (int j = 0; j < 8; j++)
                #pragma unroll
                for (int q = 0; q < 4; q++) c[i][j][q] = 0.f;

        #pragma unroll
        for (int kc = 0; kc < 9; kc++) {
            uint32_t a[2][4];
            #pragma unroll
            for (int i = 0; i < 2; i++)
                ldsm_x4(aAddr0 + (uint32_t)(i * 16 * ASTR + kc * 16) * 2,
                        a[i][0], a[i][1], a[i][2], a[i][3]);
            #pragma unroll
            for (int i = 0; i < 2; i++)
                #pragma unroll
                for (int j = 0; j < 8; j++)
                    mma16816(c[i][j], a[i], b[kc][j]);
        }
        __syncthreads();                      // A consumed

        int tn = t + MGROUPS;                 // prefetch next A (overlaps epilogue)
        if (tn < NT) {
            for (int q = tid; q < 2048; q += 256) {
                int r = q >> 4, cc = (q & 15) * 8;
                cp16(sbase + A_OFF + (uint32_t)(r * ASTR + cc) * 2,
                     &d_z[(size_t)(tn * 128 + r) * EH + cc]);
            }
            CP_COMMIT();
        }

        // epilogue: fp16 stage (conflict-free STS.32) -> int4 coalesced STG
        #pragma unroll
        for (int i = 0; i < 2; i++) {
            int row0 = wm * 32 + i * 16 + (lane >> 2);
            int col  = wn * 64 + 2 * (lane & 3);
            #pragma unroll
            for (int j = 0; j < 8; j++) {
                *(__half2*)&Cs16[row0 * CSTR16 + col + j * 8] =
                    __floats2half2_rn(c[i][j][0], c[i][j][1]);
                *(__half2*)&Cs16[(row0 + 8) * CSTR16 + col + j * 8] =
                    __floats2half2_rn(c[i][j][2], c[i][j][3]);
            }
        }
        __syncthreads();
        #pragma unroll
        for (int p = 0; p < 8; p++) {
            int idx = tid + 256 * p;
            int r = idx >> 4, c8 = (idx & 15) * 8;
            int4 v = *(int4*)&Cs16[r * CSTR16 + c8];
            *(int4*)&d_ew[(size_t)(t * 128 + r) * DD + n0 + c8] = v;
        }
        // next-tile STS to Cs16 is separated by CP_WAIT+sync+mma+sync -> safe
    }
}

// ---------------- per-step kernels -------------------------------------------
// warp per edge, LDG.128 rows: iter i covers rows 4i..4i+3 (512B coalesced)
__global__ void scatter_kernel(const int* __restrict__ src, const int* __restrict__ dst) {
    int wg   = (blockIdx.x * blockDim.x + threadIdx.x) >> 5;
    int lane = threadIdx.x & 31;
    if (wg >= E_N) return;
    int se = __ldg(&src[wg]), de = __ldg(&dst[wg]);
    float2 hv = ((const float2*)(d_h + (size_t)se * D))[lane];
    const int4* W4 = (const int4*)(d_ew + (size_t)wg * DD);
    const int rsub = lane >> 3;
    const int cg   = lane & 7;
    float acc[8] = {0.f, 0.f, 0.f, 0.f, 0.f, 0.f, 0.f, 0.f};

    #pragma unroll
    for (int i = 0; i < 16; i++) {
        int r = 4 * i + rsub;
        int4 wv = __ldg(&W4[r * 8 + cg]);
        float hx = __shfl_sync(0xffffffffu, hv.x, 2 * i + (lane >> 4));
        float hy = __shfl_sync(0xffffffffu, hv.y, 2 * i + (lane >> 4));
        float hr = (rsub & 1) ? hy : hx;
        const __half2* wh = (const __half2*)&wv;
        #pragma unroll
        for (int q = 0; q < 4; q++) {
            float2 f = __half22float2(wh[q]);
            acc[2 * q]     = fmaf(hr, f.x, acc[2 * q]);
            acc[2 * q + 1] = fmaf(hr, f.y, acc[2 * q + 1]);
        }
    }
    #pragma unroll
    for (int j = 0; j < 8; j++) {
        acc[j] += __shfl_xor_sync(0xffffffffu, acc[j], 8);
        acc[j] += __shfl_xor_sync(0xffffffffu, acc[j], 16);
    }
    if (lane < 8) {
        float* nb = d_neigh + (size_t)de * D + lane * 8;
        #pragma unroll
        for (int j = 0; j < 8; j++) atomicAdd(nb + j, acc[j]);
    }
}

// GRU: G = [relu(neigh+cb) | h](fp16) @ Wg^T (fp32 accum), fused gates +
// h update + neigh re-zero. block 256 thr, tile M=64 nodes x N=256 gate-rows.
#include <mma.h>
using namespace nvcuda;
#define GW_STR 136
#define GC_STR 264
#define GX_OFF (256 * GW_STR * 2)              // 69632
#define GRU_SMEM (GX_OFF + 64 * GW_STR * 2)    // 87040 (Cs 64x264x4 overlays Wgs)
__global__ __launch_bounds__(256, 2) void gru_mm(const float* __restrict__ conv_b,
                                                 const float* __restrict__ bih,
                                                 const float* __restrict__ bhh) {
    extern __shared__ char smem[];
    __half* Wgs = (__half*)smem;
    __half* Xs  = (__half*)(smem + GX_OFF);
    float*  Cs  = (float*)smem;                // overlay after MMA
    const int tid = threadIdx.x;
    const int w = tid >> 5;
    const int wm = w & 1;
    const int wn = w >> 1;
    const int v0 = blockIdx.x * 64;

    for (int q = tid; q < 4096; q += 256) {
        int r = q >> 4, c8 = (q & 15) * 8;
        *(int4*)&Wgs[r * GW_STR + c8] = *(const int4*)&d_Wg[r * EH + c8];
    }
    for (int q = tid; q < 4096; q += 256) {
        int r = q >> 6, k = q & 63;
        float xv = fmaxf(d_neigh[(size_t)(v0 + r) * D + k] + __ldg(&conv_b[k]), 0.f);
        Xs[r * GW_STR + k]      = __float2half(xv);
        Xs[r * GW_STR + 64 + k] = __float2half(d_h[(size_t)(v0 + r) * D + k]);
    }
    __syncthreads();

    wmma::fragment<wmma::accumulator, 16, 16, 16, float> acc[8];
    #pragma unroll
    for (int f = 0; f < 8; f++) wmma::fill_fragment(acc[f], 0.f);

    #pragma unroll
    for (int kc = 0; kc < 8; kc++) {
        wmma::fragment<wmma::matrix_a, 16, 16, 16, __half, wmma::row_major> af[2];
        #pragma unroll
        for (int i = 0; i < 2; i++)
            wmma::load_matrix_sync(af[i], &Xs[(wm * 32 + i * 16) * GW_STR + kc * 16], GW_STR);
        #pragma unroll
        for (int nf = 0; nf < 4; nf++) {
            wmma::fragment<wmma::matrix_b, 16, 16, 16, __half, wmma::col_major> bf;
            wmma::load_matrix_sync(bf, &Wgs[(wn * 64 + nf * 16) * GW_STR + kc * 16], GW_STR);
            #pragma unroll
            for (int i = 0; i < 2; i++)
                wmma::mma_sync(acc[i * 4 + nf], af[i], bf, acc[i * 4 + nf]);
        }
    }

    __syncthreads();
    #pragma unroll
    for (int i = 0; i < 2; i++)
        #pragma unroll
        for (int nf = 0; nf < 4; nf++)
            wmma::store_matrix_sync(&Cs[(wm * 32 + i * 16) * GC_STR + wn * 64 + nf * 16],
                                    acc[i * 4 + nf], GC_STR, wmma::mem_row_major);
    __syncthreads();

    for (int q = tid; q < 4096; q += 256) {
        int r = q >> 6, j = q & 63;
        int v = v0 + r;
        if (v >= V_N) break;
        const float* cr = Cs + r * GC_STR;
        float g0 = cr[j], g1 = cr[64 + j], g2 = cr[128 + j], g3 = cr[192 + j];
        float rg = 1.f / (1.f + expf(-(g0 + __ldg(&bih[j])      + __ldg(&bhh[j]))));
        float zg = 1.f / (1.f + expf(-(g1 + __ldg(&bih[64 + j]) + __ldg(&bhh[64 + j]))));
        float ng = tanhf(g2 + __ldg(&bih[128 + j]) + rg * (g3 + __ldg(&bhh[128 + j])));
        size_t gi = (size_t)v * D + j;
        float hp = d_h[gi];
        d_h[gi] = (1.f - zg) * ng + zg * hp;
        d_neigh[gi] = 0.f;
    }
}

__global__ void pred_kernel(const int* __restrict__ src, const int* __restrict__ dst,
                            const float* __restrict__ pW, const float* __restrict__ pb,
                            float* __restrict__ out) {
    int wg   = (blockIdx.x * blockDim.x + threadIdx.x) >> 5;
    int lane = threadIdx.x & 31;
    if (wg >= E_N) return;
    int se = src[wg], de = dst[wg];
    float2 a  = ((const float2*)(d_h + (size_t)se * D))[lane];
    float2 b  = ((const float2*)(d_h + (size_t)de * D))[lane];
    float2 w1 = ((const float2*)pW)[lane];
    float2 w2 = ((const float2*)pW)[32 + lane];
    float acc = a.x * w1.x + a.y * w1.y + b.x * w2.x + b.y * w2.y;
    #pragma unroll
    for (int off = 16; off > 0; off >>= 1)
        acc += __shfl_down_sync(0xffffffffu, acc, off);
    if (lane == 0) out[wg] = acc + pb[0];
}

// ---------------- launch ------------------------------------------------------
extern "C" void kernel_launch(void* const* d_in, const int* in_sizes, int n_in,
                              void* d_out, int out_size) {
    const float* node_feats = (const float*)d_in[0];
    const float* edge_feats = (const float*)d_in[1];
    const int*   src        = (const int*)d_in[2];
    const int*   dst        = (const int*)d_in[3];
    const float* proj_W     = (const float*)d_in[4];
    const float* proj_b     = (const float*)d_in[5];
    const float* en_W1      = (const float*)d_in[6];
    const float* en_b1      = (const float*)d_in[7];
    const float* en_W2      = (const float*)d_in[8];
    const float* en_b2      = (const float*)d_in[9];
    const float* conv_b     = (const float*)d_in[10];
    const float* gru_Wih    = (const float*)d_in[11];
    const float* gru_Whh    = (const float*)d_in[12];
    const float* gru_bih    = (const float*)d_in[13];
    const float* gru_bhh    = (const float*)d_in[14];
    const float* pred_W     = (const float*)d_in[15];
    const float* pred_b     = (const float*)d_in[16];
    float* out = (float*)d_out;

    static int attr_set = 0;
    if (!attr_set) {
        cudaFuncSetAttribute(ew_gemm, cudaFuncAttributeMaxDynamicSharedMemorySize, EW_SMEM);
        cudaFuncSetAttribute(gru_mm, cudaFuncAttributeMaxDynamicSharedMemorySize, GRU_SMEM);
        attr_set = 1;
    }

    zhid_kernel<<<E_N / 16, 256>>>(edge_feats, en_W1, en_b1);            // 1
    proj_kernel<<<V_N / 16, 256>>>(node_feats, proj_W, proj_b);          // 2 (+neigh zero)
    dim3 gg(NSLABS, MGROUPS);                                            // (32, 4)
    ew_gemm<<<gg, 256, EW_SMEM>>>(en_W2, en_b2);                         // 3

    for (int s = 0; s < STEPS; s++) {
        scatter_kernel<<<E_N / 8, 256>>>(src, dst);                      // 4 on s=0 (profiled)
        if (s == 0) prep_wg<<<(256 * EH + 255) / 256, 256>>>(gru_Wih, gru_Whh);
        gru_mm<<<V_PAD / 64, 256, GRU_SMEM>>>(conv_b, gru_bih, gru_bhh);
    }
    pred_kernel<<<E_N / 8, 256>>>(src, dst, pred_W, pred_b, out);
}

// round 10
// speedup vs baseline: 1.0098x; 1.0098x over previous
#include <cuda_runtime.h>
#include <cuda_fp16.h>
#include <cstdint>

#define V_N 20000
#define V_PAD 20032      // 313 * 64
#define E_N 40000
#define E_PAD 40064      // 313 * 128
#define NT 313           // 128-row M tiles in ew gemm
#define NIN 74
#define EIN 12
#define D 64
#define EH 128
#define DD 4096
#define STEPS 6

// ---------------- scratch (static device globals; zero-initialized) ---------
__device__ float  d_h[V_PAD * D];
__device__ float  d_neigh[V_PAD * D];
__device__ __half d_z[E_PAD * EH];
__device__ __half d_ew[(size_t)E_PAD * DD];
__device__ __half d_Wg[256 * EH];              // packed GRU weights (fp16)

// ---------------- asm helpers -------------------------------------------------
__device__ __forceinline__ uint32_t smem_u32(const void* p) {
    uint32_t a;
    asm("{ .reg .u64 t; cvta.to.shared.u64 t, %1; cvt.u32.u64 %0, t; }" : "=r"(a) : "l"(p));
    return a;
}
__device__ __forceinline__ void cp16(uint32_t s, const void* g) {
    asm volatile("cp.async.cg.shared.global [%0], [%1], 16;" :: "r"(s), "l"(g));
}
#define CP_COMMIT() asm volatile("cp.async.commit_group;" ::: "memory")
#define CP_WAIT0()  asm volatile("cp.async.wait_group 0;" ::: "memory")

__device__ __forceinline__ void ldsm_x4(uint32_t addr, uint32_t& r0, uint32_t& r1,
                                        uint32_t& r2, uint32_t& r3) {
    asm volatile("ldmatrix.sync.aligned.m8n8.x4.shared.b16 {%0,%1,%2,%3}, [%4];"
                 : "=r"(r0), "=r"(r1), "=r"(r2), "=r"(r3) : "r"(addr));
}
__device__ __forceinline__ void ldsm_x2(uint32_t addr, uint32_t& r0, uint32_t& r1) {
    asm volatile("ldmatrix.sync.aligned.m8n8.x2.shared.b16 {%0,%1}, [%2];"
                 : "=r"(r0), "=r"(r1) : "r"(addr));
}
__device__ __forceinline__ void mma16816(float* c, const uint32_t* a, const uint32_t* b) {
    asm volatile("mma.sync.aligned.m16n8k16.row.col.f32.f16.f16.f32 "
                 "{%0,%1,%2,%3}, {%4,%5,%6,%7}, {%8,%9}, {%0,%1,%2,%3};"
                 : "+f"(c[0]), "+f"(c[1]), "+f"(c[2]), "+f"(c[3])
                 : "r"(a[0]), "r"(a[1]), "r"(a[2]), "r"(a[3]), "r"(b[0]), "r"(b[1]));
}

// ---------------- fused prep: zhid (2500 blk) + proj (1250 blk) + wg (128 blk)
#define ZB 2500
#define PB 1250
#define WB 128
__global__ void prep_all(const float* __restrict__ ef,  const float* __restrict__ W1,
                         const float* __restrict__ b1,  const float* __restrict__ nf,
                         const float* __restrict__ pW,  const float* __restrict__ pb,
                         const float* __restrict__ Wih, const float* __restrict__ Whh) {
    __shared__ char sb[24320];
    const int tid = threadIdx.x;
    const int bx  = blockIdx.x;

    if (bx < ZB) {
        // ---- zhid: d_z = relu(ef @ W1^T + b1) -> fp16, 16 edges/block
        float* W1s = (float*)sb;                 // [EIN][EH]
        float* b1s = (float*)(sb + 6144);        // [EH]
        float* efs = (float*)(sb + 6656);        // [16][EIN]
        const int e0 = bx * 16;
        for (int idx = tid; idx < EH * EIN; idx += 256) {
            int k = idx / EIN, i = idx % EIN;
            W1s[i * EH + k] = W1[idx];
        }
        for (int idx = tid; idx < 16 * EIN; idx += 256) {
            int e = idx / EIN, i = idx % EIN;
            efs[e * EIN + i] = ef[(size_t)(e0 + e) * EIN + i];
        }
        if (tid < EH) b1s[tid] = b1[tid];
        __syncthreads();
        const int k = tid & 127, g = tid >> 7;
        #pragma unroll
        for (int ee = 0; ee < 8; ee++) {
            int e = g * 8 + ee;
            float acc = b1s[k];
            #pragma unroll
            for (int i = 0; i < EIN; i++)
                acc = fmaf(W1s[i * EH + k], efs[e * EIN + i], acc);
            d_z[(size_t)(e0 + e) * EH + k] = __float2half(fmaxf(acc, 0.f));
        }
    } else if (bx < ZB + PB) {
        // ---- proj: d_h = relu(nf @ pW^T + pb); zero d_neigh. 16 nodes/block
        float* Ws  = (float*)sb;                 // [NIN][D]
        float* nfs = (float*)(sb + 18944);       // [16][NIN+2]
        float* bs  = (float*)(sb + 23808);       // [D]
        const int v0 = (bx - ZB) * 16;
        for (int idx = tid; idx < D * NIN; idx += 256) {
            int o = idx / NIN, i = idx % NIN;
            Ws[i * D + o] = pW[idx];
        }
        for (int idx = tid; idx < 16 * NIN; idx += 256) {
            int n = idx / NIN, i = idx % NIN;
            nfs[n * (NIN + 2) + i] = nf[(size_t)(v0 + n) * NIN + i];
        }
        if (tid < D) bs[tid] = pb[tid];
        __syncthreads();
        const int o = tid & 63, g = tid >> 6;
        #pragma unroll
        for (int nn = 0; nn < 4; nn++) {
            int n = g * 4 + nn;
            float acc = bs[o];
            #pragma unroll
            for (int i = 0; i < NIN; i++)
                acc = fmaf(Ws[i * D + o], nfs[n * (NIN + 2) + i], acc);
            d_h[(size_t)(v0 + n) * D + o] = fmaxf(acc, 0.f);
            d_neigh[(size_t)(v0 + n) * D + o] = 0.f;
        }
    } else {
        // ---- prep_wg: pack GRU weights Wg[256][128]
        int idx = (bx - ZB - PB) * 256 + tid;
        if (idx < 256 * EH) {
            int r = idx >> 7, k = idx & 127;
            float v = 0.f;
            if (r < 128) {
                v = (k < 64) ? Wih[r * D + k] : Whh[r * D + (k - 64)];
            } else if (r < 192) {                // i_n: Wih rows 128..191
                if (k < 64) v = Wih[r * D + k];
            } else {                             // h_n: Whh rows 128..191
                if (k >= 64) v = Whh[(r - 64) * D + (k - 64)];
            }
            d_Wg[idx] = __float2half(v);
        }
    }
}

// ---------------- ew GEMM (R8 version: PTX mma, direct half2 epilogue) --------
// C[E_PAD,4096] = [z|1] @ [W2|b2]^T ; tile M=128 x N=128, K=144 (chunk 8 = bias)
#define ASTR 152
#define BSTR 152
#define B_BYTES   (128 * BSTR * 2)             // 38912
#define A_BYTES   (128 * ASTR * 2)             // 38912
#define A_OFF     B_BYTES
#define EW_SMEM   (A_OFF + A_BYTES)            // 77824 -> 2 CTAs/SM
#define NSLABS 32
#define MGROUPS 9

__global__ __launch_bounds__(256, 2) void ew_gemm(const float* __restrict__ W2,
                                                  const float* __restrict__ b2) {
    extern __shared__ char smem[];
    __half* Bs = (__half*)smem;
    __half* As = (__half*)(smem + A_OFF);
    const uint32_t sbase = smem_u32(smem);
    const int tid  = threadIdx.x;
    const int lane = tid & 31;
    const int w    = tid >> 5;
    const int wm   = w & 3;
    const int wn   = w >> 2;
    const int n0   = blockIdx.x * 128;
    const int by   = blockIdx.y;

    for (int q = tid; q < 4096; q += 256) {
        int n = q >> 5, k4 = (q & 31) * 4;
        float4 v = *(const float4*)&W2[(size_t)(n0 + n) * EH + k4];
        __half t4[4] = { __float2half(v.x), __float2half(v.y),
                         __float2half(v.z), __float2half(v.w) };
        *(uint2*)&Bs[n * BSTR + k4] = *(uint2*)t4;
    }
    for (int q = tid; q < 2048; q += 256) {
        int n = q >> 4, k = 128 + (q & 15);
        Bs[n * BSTR + k] = (k == 128) ? __float2half(b2[n0 + n]) : __half(0);
    }
    for (int q = tid; q < 2048; q += 256) {
        int r = q >> 4, k = 128 + (q & 15);
        As[r * ASTR + k] = (k == 128) ? __float2half(1.f) : __half(0);
    }
    for (int q = tid; q < 2048; q += 256) {
        int r = q >> 4, c = (q & 15) * 8;
        cp16(sbase + A_OFF + (uint32_t)(r * ASTR + c) * 2,
             &d_z[(size_t)(by * 128 + r) * EH + c]);
    }
    CP_COMMIT();

    const int a_r = lane & 15, a_c = (lane >> 4) * 8;
    const int b_r = lane & 7,  b_c = ((lane >> 3) & 1) * 8;
    const uint32_t aAddr0 = sbase + A_OFF + (uint32_t)((wm * 32 + a_r) * ASTR + a_c) * 2;
    const uint32_t bAddr0 = sbase + (uint32_t)((wn * 64 + b_r) * BSTR + b_c) * 2;

    const int TPT = (NT + MGROUPS - 1) / MGROUPS;
    for (int mt = 0; mt < TPT; mt++) {
        int t = by + MGROUPS * mt;
        if (t >= NT) break;
        CP_WAIT0();
        __syncthreads();

        float c[2][8][4];
        #pragma unroll
        for (int i = 0; i < 2; i++)
            #pragma unroll
            for (int j = 0; j < 8; j++)
                #pragma unroll
                for (int q = 0; q < 4; q++) c[i][j][q] = 0.f;

        #pragma unroll
        for (int kc = 0; kc < 9; kc++) {
            uint32_t a[2][4];
            #pragma unroll
            for (int i = 0; i < 2; i++)
                ldsm_x4(aAddr0 + (uint32_t)(i * 16 * ASTR + kc * 16) * 2,
                        a[i][0], a[i][1], a[i][2], a[i][3]);
            uint32_t b[8][2];
            #pragma unroll
            for (int j = 0; j < 8; j++)
                ldsm_x2(bAddr0 + (uint32_t)(j * 8 * BSTR + kc * 16) * 2,
                        b[j][0], b[j][1]);
            #pragma unroll
            for (int i = 0; i < 2; i++)
                #pragma unroll
                for (int j = 0; j < 8; j++)
                    mma16816(c[i][j], a[i], b[j]);
        }
        __syncthreads();

        int tn = t + MGROUPS;
        if (tn < NT) {
            for (int q = tid; q < 2048; q += 256) {
                int r = q >> 4, cc = (q & 15) * 8;
                cp16(sbase + A_OFF + (uint32_t)(r * ASTR + cc) * 2,
                     &d_z[(size_t)(tn * 128 + r) * EH + cc]);
            }
            CP_COMMIT();
        }

        const int rbase = t * 128 + wm * 32 + (lane >> 2);
        const int cbase = n0 + wn * 64 + 2 * (lane & 3);
        #pragma unroll
        for (int i = 0; i < 2; i++) {
            size_t rowo = (size_t)(rbase + i * 16) * DD;
            #pragma unroll
            for (int j = 0; j < 8; j++) {
                int col = cbase + j * 8;
                *(__half2*)&d_ew[rowo + col] =
                    __floats2half2_rn(c[i][j][0], c[i][j][1]);
                *(__half2*)&d_ew[rowo + 8 * DD + col] =
                    __floats2half2_rn(c[i][j][2], c[i][j][3]);
            }
        }
    }
}

// ---------------- per-step kernels -------------------------------------------
// warp per edge, LDG.128 rows (at HBM/LTS ceiling per R9 ncu)
__global__ void scatter_kernel(const int* __restrict__ src, const int* __restrict__ dst) {
    int wg   = (blockIdx.x * blockDim.x + threadIdx.x) >> 5;
    int lane = threadIdx.x & 31;
    if (wg >= E_N) return;
    int se = __ldg(&src[wg]), de = __ldg(&dst[wg]);
    float2 hv = ((const float2*)(d_h + (size_t)se * D))[lane];
    const int4* W4 = (const int4*)(d_ew + (size_t)wg * DD);
    const int rsub = lane >> 3;
    const int cg   = lane & 7;
    float acc[8] = {0.f, 0.f, 0.f, 0.f, 0.f, 0.f, 0.f, 0.f};

    #pragma unroll
    for (int i = 0; i < 16; i++) {
        int r = 4 * i + rsub;
        int4 wv = __ldg(&W4[r * 8 + cg]);
        float hx = __shfl_sync(0xffffffffu, hv.x, 2 * i + (lane >> 4));
        float hy = __shfl_sync(0xffffffffu, hv.y, 2 * i + (lane >> 4));
        float hr = (rsub & 1) ? hy : hx;
        const __half2* wh = (const __half2*)&wv;
        #pragma unroll
        for (int q = 0; q < 4; q++) {
            float2 f = __half22float2(wh[q]);
            acc[2 * q]     = fmaf(hr, f.x, acc[2 * q]);
            acc[2 * q + 1] = fmaf(hr, f.y, acc[2 * q + 1]);
        }
    }
    #pragma unroll
    for (int j = 0; j < 8; j++) {
        acc[j] += __shfl_xor_sync(0xffffffffu, acc[j], 8);
        acc[j] += __shfl_xor_sync(0xffffffffu, acc[j], 16);
    }
    if (lane < 8) {
        float* nb = d_neigh + (size_t)de * D + lane * 8;
        #pragma unroll
        for (int j = 0; j < 8; j++) atomicAdd(nb + j, acc[j]);
    }
}

// GRU: G = [relu(neigh+cb) | h](fp16) @ Wg^T (fp32 accum), fused fast-math
// gates + h update + neigh re-zero.
#include <mma.h>
using namespace nvcuda;
#define GW_STR 136
#define GC_STR 264
#define GX_OFF (256 * GW_STR * 2)              // 69632
#define GRU_SMEM (GX_OFF + 64 * GW_STR * 2)    // 87040 (Cs overlays Wgs)
__global__ __launch_bounds__(256, 2) void gru_mm(const float* __restrict__ conv_b,
                                                 const float* __restrict__ bih,
                                                 const float* __restrict__ bhh) {
    extern __shared__ char smem[];
    __half* Wgs = (__half*)smem;
    __half* Xs  = (__half*)(smem + GX_OFF);
    float*  Cs  = (float*)smem;                // overlay after MMA
    const int tid = threadIdx.x;
    const int w = tid >> 5;
    const int wm = w & 1;
    const int wn = w >> 1;
    const int v0 = blockIdx.x * 64;

    for (int q = tid; q < 4096; q += 256) {
        int r = q >> 4, c8 = (q & 15) * 8;
        *(int4*)&Wgs[r * GW_STR + c8] = *(const int4*)&d_Wg[r * EH + c8];
    }
    for (int q = tid; q < 4096; q += 256) {
        int r = q >> 6, k = q & 63;
        float xv = fmaxf(d_neigh[(size_t)(v0 + r) * D + k] + __ldg(&conv_b[k]), 0.f);
        Xs[r * GW_STR + k]      = __float2half(xv);
        Xs[r * GW_STR + 64 + k] = __float2half(d_h[(size_t)(v0 + r) * D + k]);
    }
    __syncthreads();

    wmma::fragment<wmma::accumulator, 16, 16, 16, float> acc[8];
    #pragma unroll
    for (int f = 0; f < 8; f++) wmma::fill_fragment(acc[f], 0.f);

    #pragma unroll
    for (int kc = 0; kc < 8; kc++) {
        wmma::fragment<wmma::matrix_a, 16, 16, 16, __half, wmma::row_major> af[2];
        #pragma unroll
        for (int i = 0; i < 2; i++)
            wmma::load_matrix_sync(af[i], &Xs[(wm * 32 + i * 16) * GW_STR + kc * 16], GW_STR);
        #pragma unroll
        for (int nf = 0; nf < 4; nf++) {
            wmma::fragment<wmma::matrix_b, 16, 16, 16, __half, wmma::col_major> bf;
            wmma::load_matrix_sync(bf, &Wgs[(wn * 64 + nf * 16) * GW_STR + kc * 16], GW_STR);
            #pragma unroll
            for (int i = 0; i < 2; i++)
                wmma::mma_sync(acc[i * 4 + nf], af[i], bf, acc[i * 4 + nf]);
        }
    }

    __syncthreads();
    #pragma unroll
    for (int i = 0; i < 2; i++)
        #pragma unroll
        for (int nf = 0; nf < 4; nf++)
            wmma::store_matrix_sync(&Cs[(wm * 32 + i * 16) * GC_STR + wn * 64 + nf * 16],
                                    acc[i * 4 + nf], GC_STR, wmma::mem_row_major);
    __syncthreads();

    for (int q = tid; q < 4096; q += 256) {
        int r = q >> 6, j = q & 63;
        int v = v0 + r;
        if (v >= V_N) break;
        const float* cr = Cs + r * GC_STR;
        float g0 = cr[j], g1 = cr[64 + j], g2 = cr[128 + j], g3 = cr[192 + j];
        float rg = 1.f / (1.f + __expf(-(g0 + __ldg(&bih[j])      + __ldg(&bhh[j]))));
        float zg = 1.f / (1.f + __expf(-(g1 + __ldg(&bih[64 + j]) + __ldg(&bhh[64 + j]))));
        float nx = g2 + __ldg(&bih[128 + j]) + rg * (g3 + __ldg(&bhh[128 + j]));
        float e2 = __expf(2.f * nx);
        float ng = 1.f - 2.f / (e2 + 1.f);     // tanh, saturates safely
        size_t gi = (size_t)v * D + j;
        float hp = d_h[gi];
        d_h[gi] = (1.f - zg) * ng + zg * hp;
        d_neigh[gi] = 0.f;
    }
}

__global__ void pred_kernel(const int* __restrict__ src, const int* __restrict__ dst,
                            const float* __restrict__ pW, const float* __restrict__ pb,
                            float* __restrict__ out) {
    int wg   = (blockIdx.x * blockDim.x + threadIdx.x) >> 5;
    int lane = threadIdx.x & 31;
    if (wg >= E_N) return;
    int se = src[wg], de = dst[wg];
    float2 a  = ((const float2*)(d_h + (size_t)se * D))[lane];
    float2 b  = ((const float2*)(d_h + (size_t)de * D))[lane];
    float2 w1 = ((const float2*)pW)[lane];
    float2 w2 = ((const float2*)pW)[32 + lane];
    float acc = a.x * w1.x + a.y * w1.y + b.x * w2.x + b.y * w2.y;
    #pragma unroll
    for (int off = 16; off > 0; off >>= 1)
        acc += __shfl_down_sync(0xffffffffu, acc, off);
    if (lane == 0) out[wg] = acc + pb[0];
}

// ---------------- launch ------------------------------------------------------
extern "C" void kernel_launch(void* const* d_in, const int* in_sizes, int n_in,
                              void* d_out, int out_size) {
    const float* node_feats = (const float*)d_in[0];
    const float* edge_feats = (const float*)d_in[1];
    const int*   src        = (const int*)d_in[2];
    const int*   dst        = (const int*)d_in[3];
    const float* proj_W     = (const float*)d_in[4];
    const float* proj_b     = (const float*)d_in[5];
    const float* en_W1      = (const float*)d_in[6];
    const float* en_b1      = (const float*)d_in[7];
    const float* en_W2      = (const float*)d_in[8];
    const float* en_b2      = (const float*)d_in[9];
    const float* conv_b     = (const float*)d_in[10];
    const float* gru_Wih    = (const float*)d_in[11];
    const float* gru_Whh    = (const float*)d_in[12];
    const float* gru_bih    = (const float*)d_in[13];
    const float* gru_bhh    = (const float*)d_in[14];
    const float* pred_W     = (const float*)d_in[15];
    const float* pred_b     = (const float*)d_in[16];
    float* out = (float*)d_out;

    static int attr_set = 0;
    if (!attr_set) {
        cudaFuncSetAttribute(ew_gemm, cudaFuncAttributeMaxDynamicSharedMemorySize, EW_SMEM);
        cudaFuncSetAttribute(gru_mm, cudaFuncAttributeMaxDynamicSharedMemorySize, GRU_SMEM);
        attr_set = 1;
    }

    prep_all<<<ZB + PB + WB, 256>>>(edge_feats, en_W1, en_b1, node_feats,
                                    proj_W, proj_b, gru_Wih, gru_Whh);   // 1
    dim3 gg(NSLABS, MGROUPS);                                            // (32, 9)
    ew_gemm<<<gg, 256, EW_SMEM>>>(en_W2, en_b2);                         // 2

    for (int s = 0; s < STEPS; s++) {
        scatter_kernel<<<E_N / 8, 256>>>(src, dst);                      // 3 on s=0
        gru_mm<<<V_PAD / 64, 256, GRU_SMEM>>>(conv_b, gru_bih, gru_bhh); // 4 on s=0 (profiled)
    }
    pred_kernel<<<E_N / 8, 256>>>(src, dst, pred_W, pred_b, out);
}